// round 14
// baseline (speedup 1.0000x reference)
#include <cuda_runtime.h>
#include <cstdint>

#define BB 512
#define LL 2048
#define CC 32
#define FULLM 0xffffffffu
#define LOG2E 1.4426950408889634f

__device__ double g_logz[BB];
__device__ double g_score[BB];
__device__ float  g_w[BB * CC], g_u[BB * CC];
__device__ float  g_P2[BB * CC * CC], g_P3[BB * CC * CC];  // S2^T, S3^T row-major
__device__ float  g_sw[BB], g_su[BB], g_s2[BB], g_s3[BB];  // log2 scales
__device__ int    g_bt[BB];
__device__ int    g_ticket;

__device__ __forceinline__ float rcp_approx(float x){float r;asm("rcp.approx.f32 %0,%1;":"=f"(r):"f"(x));return r;}
__device__ __forceinline__ float ex2_approx(float x){float r;asm("ex2.approx.f32 %0,%1;":"=f"(r):"f"(x));return r;}
__device__ __forceinline__ float lg2_approx(float x){float r;asm("lg2.approx.f32 %0,%1;":"=f"(r):"f"(x));return r;}
__device__ __forceinline__ uint32_t pack_bf16(float lo,float hi){
    uint32_t r;asm("cvt.rn.satfinite.bf16x2.f32 %0,%1,%2;":"=r"(r):"f"(hi),"f"(lo));return r;}
__device__ __forceinline__ unsigned long long mul2(unsigned long long a,unsigned long long b){
    unsigned long long r;asm("mul.rn.f32x2 %0,%1,%2;":"=l"(r):"l"(a),"l"(b));return r;}
__device__ __forceinline__ void fma2(unsigned long long&c,unsigned long long a,unsigned long long b){
    asm("fma.rn.f32x2 %0,%1,%2,%0;":"+l"(c):"l"(a),"l"(b));}
__device__ __forceinline__ unsigned long long add2(unsigned long long a,unsigned long long b){
    unsigned long long r;asm("add.rn.f32x2 %0,%1,%2;":"=l"(r):"l"(a),"l"(b));return r;}

__device__ __forceinline__ void mma_z(float d[4],const uint32_t a[4],uint32_t b0,uint32_t b1){
    asm("mma.sync.aligned.m16n8k16.row.col.f32.bf16.bf16.f32 "
        "{%0,%1,%2,%3},{%4,%5,%6,%7},{%8,%9},{%10,%10,%10,%10};"
        :"=f"(d[0]),"=f"(d[1]),"=f"(d[2]),"=f"(d[3])
        :"r"(a[0]),"r"(a[1]),"r"(a[2]),"r"(a[3]),"r"(b0),"r"(b1),"f"(0.f));}
__device__ __forceinline__ void mma_a(float d[4],const uint32_t a[4],uint32_t b0,uint32_t b1){
    asm("mma.sync.aligned.m16n8k16.row.col.f32.bf16.bf16.f32 "
        "{%0,%1,%2,%3},{%4,%5,%6,%7},{%8,%9},{%0,%1,%2,%3};"
        :"+f"(d[0]),"+f"(d[1]),"+f"(d[2]),"+f"(d[3])
        :"r"(a[0]),"r"(a[1]),"r"(a[2]),"r"(a[3]),"r"(b0),"r"(b1));}

// ---------------- fp32 vector core (R4, best measured) ----------------
#define CORE(PAR_,EE_) do{                                                    \
    __syncwarp();                                                             \
    const ulonglong2* pv_=(const ulonglong2*)(sv[(PAR_)]);                    \
    ulonglong2 q0_=pv_[0],q1_=pv_[1],q2_=pv_[2],q3_=pv_[3];                   \
    ulonglong2 q4_=pv_[4],q5_=pv_[5],q6_=pv_[6],q7_=pv_[7];                   \
    unsigned long long c0_=mul2(q0_.x,tp[0]),c1_=mul2(q0_.y,tp[1]);           \
    unsigned long long c2_=mul2(q1_.x,tp[2]),c3_=mul2(q1_.y,tp[3]);           \
    unsigned long long c4_=mul2(q2_.x,tp[4]),c5_=mul2(q2_.y,tp[5]);           \
    unsigned long long c6_=mul2(q3_.x,tp[6]),c7_=mul2(q3_.y,tp[7]);           \
    fma2(c0_,q4_.x,tp[8]);fma2(c1_,q4_.y,tp[9]);                              \
    fma2(c2_,q5_.x,tp[10]);fma2(c3_,q5_.y,tp[11]);                            \
    fma2(c4_,q6_.x,tp[12]);fma2(c5_,q6_.y,tp[13]);                            \
    fma2(c6_,q7_.x,tp[14]);fma2(c7_,q7_.y,tp[15]);                            \
    unsigned long long s__=add2(add2(add2(c0_,c1_),add2(c2_,c3_)),            \
                                add2(add2(c4_,c5_),add2(c6_,c7_)));           \
    float sl_,sh_;                                                            \
    asm("mov.b64 {%0,%1},%2;":"=f"(sl_),"=f"(sh_):"l"(s__));                  \
    vn=(sl_+sh_)*(EE_);                                                       \
    sv[(PAR_)^1][lane]=vn;                                                    \
}while(0)

#define PREP_EE(EVN_,RN_) do{                                                 \
    if(RN_){float v0b_=__shfl_sync(FULLM,vn,0);                               \
        ee=ex2_approx(EVN_)*rcp_approx(v0b_); Ml2+=lg2_approx(v0b_);          \
    } else ee=ex2_approx(EVN_);                                               \
}while(0)

// fwd: 511 steps t=1..511. bwd: 511 steps (rows 2046..1536) + 1 plain step.
template<bool BWD>
__device__ float run_vec(const float* __restrict__ ep, const float* __restrict__ T,
                         int lane, float (*sv)[CC], float& vout)
{
    unsigned long long tp[16];
#pragma unroll
    for(int k=0;k<16;++k){
        float a,c;
        if(!BWD){a=__expf(T[lane*CC+2*k]);     c=__expf(T[lane*CC+2*k+1]);}
        else    {a=__expf(T[(2*k)*CC+lane]);   c=__expf(T[(2*k+1)*CC+lane]);}
        asm("mov.b64 %0,{%1,%2};":"=l"(tp[k]):"f"(a),"f"(c));
    }
    const long D = BWD ? -(long)CC : (long)CC;
    float ebuf[8];
#pragma unroll
    for(int k=0;k<8;++k) ebuf[k]=ep[D*(1+k)]*LOG2E;
    float vn=__expf(ep[0]);
    sv[1][lane]=vn;
    float Ml2, ee;
    {   float v0=__shfl_sync(FULLM,vn,0);
        ee=ex2_approx(ebuf[0])*rcp_approx(v0); Ml2=lg2_approx(v0); }
    const float* pf=ep+D*9;
#pragma unroll 1
    for(int blk=0;blk<63;++blk){           // t = 1..504
#pragma unroll
        for(int k=0;k<8;++k){
            ebuf[k]=pf[D*k]*LOG2E;
            CORE((1+k)&1, ee);
            PREP_EE(ebuf[(k+1)&7],(k&3)==3);
        }
        pf+=D*8;
    }
#pragma unroll
    for(int k=0;k<7;++k){                  // t = 505..511
        CORE((1+k)&1, ee);
        if(k<6) PREP_EE(ebuf[k+1],(k&3)==3);
    }
    if(BWD){ ee=1.f; CORE(0, ee); }        // final plain M multiply
    vout=vn;
    return Ml2;
}

// ---------------- matrix segment: P <- (P*B)*D_t, 512 steps ----------------
__device__ __forceinline__ void prep_ef(float ef[8],float raw,int s0,int s1){
    float ex_=ex2_approx(raw*LOG2E);
#pragma unroll
    for(int j=0;j<4;++j){
        ef[2*j]  =__shfl_sync(FULLM,ex_,s0+8*j);
        ef[2*j+1]=__shfl_sync(FULLM,ex_,s1+8*j);
    }
}

#define MAT_STEP(NORM_) do{                                                   \
    uint32_t A_[2][2][4];                                                     \
    _Pragma("unroll") for(int mt=0;mt<2;++mt)                                 \
    _Pragma("unroll") for(int kt=0;kt<2;++kt){                                \
        A_[mt][kt][0]=pack_bf16(fv[mt][2*kt][0],  fv[mt][2*kt][1]);           \
        A_[mt][kt][1]=pack_bf16(fv[mt][2*kt][2],  fv[mt][2*kt][3]);           \
        A_[mt][kt][2]=pack_bf16(fv[mt][2*kt+1][0],fv[mt][2*kt+1][1]);         \
        A_[mt][kt][3]=pack_bf16(fv[mt][2*kt+1][2],fv[mt][2*kt+1][3]);         \
    }                                                                         \
    float d_[2][4][4];                                                        \
    _Pragma("unroll") for(int mt=0;mt<2;++mt)                                 \
    _Pragma("unroll") for(int nt=0;nt<4;++nt)                                 \
        mma_z(d_[mt][nt],A_[mt][0],Bf[0][nt][0],Bf[0][nt][1]);                \
    _Pragma("unroll") for(int mt=0;mt<2;++mt)                                 \
    _Pragma("unroll") for(int nt=0;nt<4;++nt)                                 \
        mma_a(d_[mt][nt],A_[mt][1],Bf[1][nt][0],Bf[1][nt][1]);                \
    _Pragma("unroll") for(int mt=0;mt<2;++mt)                                 \
    _Pragma("unroll") for(int nt=0;nt<4;++nt){                                \
        fv[mt][nt][0]=d_[mt][nt][0]*ef[2*nt];                                 \
        fv[mt][nt][1]=d_[mt][nt][1]*ef[2*nt+1];                               \
        fv[mt][nt][2]=d_[mt][nt][2]*ef[2*nt];                                 \
        fv[mt][nt][3]=d_[mt][nt][3]*ef[2*nt+1];                               \
    }                                                                         \
    if(NORM_){                                                                \
        float v0_=__shfl_sync(FULLM,fv[0][0][0],0);                           \
        float r_=rcp_approx(v0_); Ml2+=lg2_approx(v0_);                       \
        _Pragma("unroll") for(int mt=0;mt<2;++mt)                             \
        _Pragma("unroll") for(int nt=0;nt<4;++nt)                             \
        _Pragma("unroll") for(int q=0;q<4;++q) fv[mt][nt][q]*=r_;             \
    }                                                                         \
}while(0)

__device__ float run_mat(int b,int T0,const float* __restrict__ em,
                         const float* __restrict__ T,
                         float* __restrict__ gP,int lane)
{
    const int tid=lane&3, gid=lane>>2, s0=2*tid, s1=s0+1;
    // B[k][n] = exp(T[n][k])  (same as forward-vector B)
    uint32_t Bf[2][4][2];
#pragma unroll
    for(int kt=0;kt<2;++kt)
#pragma unroll
    for(int nt=0;nt<4;++nt){
        int n=nt*8+gid, k0=kt*16+s0;
        Bf[kt][nt][0]=pack_bf16(__expf(T[n*CC+k0]),  __expf(T[n*CC+k0+1]));
        Bf[kt][nt][1]=pack_bf16(__expf(T[n*CC+k0+8]),__expf(T[n*CC+k0+9]));
    }
    float fv[2][4][4];
#pragma unroll
    for(int mt=0;mt<2;++mt)
#pragma unroll
    for(int nt=0;nt<4;++nt)
#pragma unroll
    for(int q=0;q<4;++q){
        int r=16*mt+gid+((q>>1)?8:0), c=8*nt+s0+(q&1);
        fv[mt][nt][q]=(r==c)?1.f:0.f;
    }
    float Ml2=0.f;
    const float* ep=em+lane;
    float ebuf[8];
#pragma unroll
    for(int k=0;k<8;++k) ebuf[k]=ep[(size_t)(T0+k)*CC];
    float ef[8];
    prep_ef(ef,ebuf[0],s0,s1);
    const float* pf=ep+(size_t)(T0+8)*CC;
#pragma unroll 1
    for(int blk=0;blk<64;++blk){           // 512 steps, rows T0..T0+511
#pragma unroll
        for(int k=0;k<8;++k){
            float rawn=ebuf[(k+1)&7];
            ebuf[k]=pf[k*CC];
            MAT_STEP((k&3)==3);
            prep_ef(ef,rawn,s0,s1);
        }
        pf+=8*CC;
    }
    // store P row-major
#pragma unroll
    for(int mt=0;mt<2;++mt)
#pragma unroll
    for(int nt=0;nt<4;++nt)
#pragma unroll
    for(int h=0;h<2;++h){
        int r=16*mt+gid+8*h, c=8*nt+s0;
        *(float2*)&gP[(size_t)b*1024 + r*32 + c]=
            make_float2(fv[mt][nt][2*h],fv[mt][nt][2*h+1]);
    }
    return Ml2;
}

__global__ void crf_init(){
    int i=threadIdx.x;
    if(i<BB) g_bt[i]=0;
    if(i==BB) g_ticket=0;
}

__device__ __forceinline__ void gticket_finish(int lane,float* out){
    int last=0;
    if(lane==0){__threadfence(); last=(atomicAdd(&g_ticket,1)==2*BB-1);}
    last=__shfl_sync(FULLM,last,0);
    if(last){
        __threadfence();
        double acc=0.0;
        for(int i=lane;i<BB;i+=32) acc+=__ldcg(&g_logz[i])-__ldcg(&g_score[i]);
#pragma unroll
        for(int o=16;o;o>>=1) acc+=__shfl_xor_sync(FULLM,acc,o);
        if(lane==0) out[0]=(float)(acc/(double)BB);
    }
}

// 4th arrival per batch: logZ = ln2*(sum scales) + ln(u . S3 S2 w)
__device__ void arrive_batch(int b,int lane,float* out){
    int go=0;
    if(lane==0){__threadfence(); go=(atomicAdd(&g_bt[b],1)==3);}
    go=__shfl_sync(FULLM,go,0);
    if(!go) return;
    __threadfence();
    double wv=(double)__ldcg(&g_w[b*CC+lane]);
    const float* p2=&g_P2[(size_t)b*1024];
    double y1=0.0;
#pragma unroll 4
    for(int j=0;j<32;++j) y1+=(double)__ldcg(&p2[j*32+lane])*__shfl_sync(FULLM,wv,j);
    const float* p3=&g_P3[(size_t)b*1024];
    double y2=0.0;
#pragma unroll 4
    for(int j=0;j<32;++j) y2+=(double)__ldcg(&p3[j*32+lane])*__shfl_sync(FULLM,y1,j);
    double s=(double)__ldcg(&g_u[b*CC+lane])*y2;
#pragma unroll
    for(int o=16;o;o>>=1) s+=__shfl_xor_sync(FULLM,s,o);
    if(lane==0){
        double m=(double)__ldcg(&g_sw[b])+(double)__ldcg(&g_su[b])
                +(double)__ldcg(&g_s2[b])+(double)__ldcg(&g_s3[b]);
        g_logz[b]=m*0.6931471805599453+log(s);
    }
    gticket_finish(lane,out);
}

// blocks: [0,512) fwd vec | [512,1024) bwd vec | [1024,2048) matrix segs
//         | [2048,2560) path score
__global__ void __launch_bounds__(CC) crf_main(
    const float* __restrict__ emissions,
    const float* __restrict__ transitions,
    const int*   __restrict__ tags,
    const int*   __restrict__ mask,
    float*       __restrict__ out)
{
    __shared__ __align__(16) float sv[2][CC];
    const int lane=threadIdx.x, bid=blockIdx.x;

    if(bid<2*BB){
        const int b=bid&(BB-1);
        const bool isF=bid<BB;
        const float* em=emissions+(size_t)b*LL*CC;
        float vout, Ml2;
        if(isF) Ml2=run_vec<false>(em+lane,transitions,lane,sv,vout);
        else    Ml2=run_vec<true >(em+(size_t)(LL-1)*CC+lane,transitions,lane,sv,vout);
        (isF?g_w:g_u)[b*CC+lane]=vout;
        if(lane==0) (isF?g_sw:g_su)[b]=Ml2;
        arrive_batch(b,lane,out);
    } else if(bid<4*BB){
        const int idx=bid-2*BB, seg=idx>>9, b=idx&(BB-1);
        const float* em=emissions+(size_t)b*LL*CC;
        float Ml2=run_mat(b, 512+512*seg, em, transitions,
                          seg?g_P3:g_P2, lane);
        if(lane==0) (seg?g_s3:g_s2)[b]=Ml2;
        arrive_batch(b,lane,out);
    } else {
        const int b=bid-4*BB;
        const int* tg=tags+(size_t)b*LL;
        const int* mk=mask+(size_t)b*LL;
        const float* eb=emissions+(size_t)b*LL*CC;
        int ms=0;
        for(int t=lane;t<LL;t+=32) ms+=mk[t];
#pragma unroll
        for(int o=16;o;o>>=1) ms+=__shfl_xor_sync(FULLM,ms,o);
        double acc=0.0;
        for(int t=lane;t<LL-1;t+=32){
            int a=tg[t],c=tg[t+1];
            acc+=(double)(eb[t*CC+a]*(float)mk[t])
               +(double)(transitions[a*CC+c]*(float)mk[t+1]);
        }
#pragma unroll
        for(int o=16;o;o>>=1) acc+=__shfl_xor_sync(FULLM,acc,o);
        if(lane==0){
            int li=ms-1; if(li<0) li=0;
            int mc=ms;  if(mc<1) mc=1;
            acc+=(double)eb[(mc-1)*CC+tg[li]];
            g_score[b]=acc;
        }
        gticket_finish(lane,out);
    }
}

extern "C" void kernel_launch(void* const* d_in,const int* in_sizes,int n_in,
                              void* d_out,int out_size){
    const float* emissions  =(const float*)d_in[0];
    const float* transitions=(const float*)d_in[1];
    const int*   tags       =(const int*)d_in[2];
    const int*   mask       =(const int*)d_in[3];
    (void)in_sizes;(void)n_in;(void)out_size;
    crf_init<<<1,BB+32>>>();
    crf_main<<<5*BB,CC>>>(emissions,transitions,tags,mask,(float*)d_out);
}